// round 5
// baseline (speedup 1.0000x reference)
#include <cuda_runtime.h>
#include <cuda_bf16.h>
#include <cstdint>

typedef unsigned long long u64;

// ---------------------------------------------------------------------------
// Problem constants
// ---------------------------------------------------------------------------
#define SEQ   512
#define BATCH 64
#define HID   1024
#define G4    4096            // 4*HID
#define MROWS (SEQ * BATCH)   // 32768

// ---------------------------------------------------------------------------
// Scratch (device globals — no allocation allowed)
// ---------------------------------------------------------------------------
__device__ float g_proj[(size_t)MROWS * G4];          // [T*B, 4H] x-projection
__device__ unsigned g_bar;                            // grid barrier counter
__device__ unsigned g_flag;                           // grid barrier release
__device__ __align__(16) __nv_bfloat16 g_Ahi[(size_t)MROWS * HID];
__device__ __align__(16) __nv_bfloat16 g_Alo[(size_t)MROWS * HID];
__device__ __align__(16) __nv_bfloat16 g_Whi[(size_t)G4 * HID];
__device__ __align__(16) __nv_bfloat16 g_Wlo[(size_t)G4 * HID];
__device__ __align__(16) __nv_bfloat16 g_hhi[2][BATCH * HID];  // h hi, [b][j]
__device__ __align__(16) __nv_bfloat16 g_hlo[2][BATCH * HID];  // h lo, [b][j]

// ---------------------------------------------------------------------------
// Helpers
// ---------------------------------------------------------------------------
__device__ __forceinline__ uint32_t smem_u32(const void* p) {
    uint32_t a;
    asm("{ .reg .u64 t; cvta.to.shared.u64 t, %1; cvt.u32.u64 %0, t; }"
        : "=r"(a) : "l"(p));
    return a;
}
__device__ __forceinline__ void ldsm4(uint32_t* r, uint32_t addr) {
    asm volatile("ldmatrix.sync.aligned.m8n8.x4.shared.b16 {%0,%1,%2,%3}, [%4];"
                 : "=r"(r[0]), "=r"(r[1]), "=r"(r[2]), "=r"(r[3]) : "r"(addr));
}
__device__ __forceinline__ void ldsm2(uint32_t* r, uint32_t addr) {
    asm volatile("ldmatrix.sync.aligned.m8n8.x2.shared.b16 {%0,%1}, [%2];"
                 : "=r"(r[0]), "=r"(r[1]) : "r"(addr));
}
__device__ __forceinline__ void mma16816(float* c, const uint32_t* a, const uint32_t* b) {
    asm volatile("mma.sync.aligned.m16n8k16.row.col.f32.bf16.bf16.f32 "
                 "{%0,%1,%2,%3}, {%4,%5,%6,%7}, {%8,%9}, {%0,%1,%2,%3};"
                 : "+f"(c[0]), "+f"(c[1]), "+f"(c[2]), "+f"(c[3])
                 : "r"(a[0]), "r"(a[1]), "r"(a[2]), "r"(a[3]),
                   "r"(b[0]), "r"(b[1]));
}
#define CP_ASYNC16(sdst, gsrc) \
    asm volatile("cp.async.cg.shared.global [%0], [%1], 16;" :: "r"(sdst), "l"(gsrc))
#define CP_COMMIT() asm volatile("cp.async.commit_group;" ::: "memory")
#define CP_WAIT1()  asm volatile("cp.async.wait_group 1;" ::: "memory")
#define CP_WAIT2()  asm volatile("cp.async.wait_group 2;" ::: "memory")

__device__ __forceinline__ float sigmoidf_(float x) { return 1.0f / (1.0f + __expf(-x)); }
__device__ __forceinline__ float tanhf_(float x) { return 2.0f / (1.0f + __expf(-2.0f * x)) - 1.0f; }
__device__ __forceinline__ float sel4(float v0, float v1, float v2, float v3, int i) {
    float r = v0;
    if (i == 1) r = v1; else if (i == 2) r = v2; else if (i == 3) r = v3;
    return r;
}

// ---------------------------------------------------------------------------
// Zero h buffers + barrier state
// ---------------------------------------------------------------------------
__global__ void zero_state_kernel() {
    int i = blockIdx.x * blockDim.x + threadIdx.x;
    if (i == 0) { g_bar = 0u; g_flag = 0u; }
    const uint4 z = make_uint4(0, 0, 0, 0);
    if (i < (int)(sizeof(g_hhi) / 16)) {
        reinterpret_cast<uint4*>(&g_hhi[0][0])[i] = z;
        reinterpret_cast<uint4*>(&g_hlo[0][0])[i] = z;
    }
}

// ---------------------------------------------------------------------------
// fp32 -> bf16 hi/lo split
// ---------------------------------------------------------------------------
__global__ void split_kernel(const float* __restrict__ src,
                             __nv_bfloat16* __restrict__ hi,
                             __nv_bfloat16* __restrict__ lo, int n4) {
    int i = blockIdx.x * blockDim.x + threadIdx.x;
    int stride = gridDim.x * blockDim.x;
    for (; i < n4; i += stride) {
        float4 v = reinterpret_cast<const float4*>(src)[i];
        __nv_bfloat16 h[4], l[4];
        float vv[4] = {v.x, v.y, v.z, v.w};
#pragma unroll
        for (int k = 0; k < 4; k++) {
            h[k] = __float2bfloat16_rn(vv[k]);
            l[k] = __float2bfloat16_rn(vv[k] - __bfloat162float(h[k]));
        }
        reinterpret_cast<uint2*>(hi)[i] = *reinterpret_cast<uint2*>(h);
        reinterpret_cast<uint2*>(lo)[i] = *reinterpret_cast<uint2*>(l);
    }
}

// ---------------------------------------------------------------------------
// bf16x3 GEMM via mma.sync, 3-stage cp.async ring.
// g_proj[m,n] = sum_k A[m,k]*W[n,k] + b1[n] + b2[n]
// ---------------------------------------------------------------------------
#define KSTG       32
#define NSTAGES    (HID / KSTG)
#define PITCH_B    80
#define REG_BYTES  (128 * PITCH_B)
#define STG_BYTES  (4 * REG_BYTES)       // 40960
#define GEMM_SMEM  (3 * STG_BYTES)       // 122880

__device__ __forceinline__ void stage_load(uint32_t sbase, int s, int m0, int n0,
                                           int tid) {
    const int kt = s * KSTG;
    const uint32_t dst = sbase + (s % 3) * STG_BYTES;
#pragma unroll
    for (int r = 0; r < 4; r++) {
        const __nv_bfloat16* src =
            (r == 0) ? g_Ahi : (r == 1) ? g_Alo : (r == 2) ? g_Whi : g_Wlo;
        const int rb = (r < 2) ? m0 : n0;
#pragma unroll
        for (int j = 0; j < 2; j++) {
            const int chunk = tid + j * 256;
            const int row = chunk >> 2;
            const int kc = chunk & 3;
            const void* g = src + (size_t)(rb + row) * HID + kt + kc * 8;
            const uint32_t sd = dst + r * REG_BYTES + row * PITCH_B + kc * 16;
            CP_ASYNC16(sd, g);
        }
    }
}

__global__ __launch_bounds__(256, 1) void mma_gemm_kernel(
    const float* __restrict__ bias1, const float* __restrict__ bias2)
{
    extern __shared__ char dsm[];
    __shared__ float s_bias[128];

    const int tid = threadIdx.x;
    const int wid = tid >> 5;
    const int lane = tid & 31;
    const int m0 = blockIdx.x * 128;
    const int n0 = blockIdx.y * 128;
    const int wm = (wid & 3) * 32;
    const int wn = (wid >> 2) * 64;

    const uint32_t sbase = smem_u32(dsm);

    if (tid < 128) s_bias[tid] = bias1[n0 + tid] + bias2[n0 + tid];

    float acc[2][8][4];
#pragma unroll
    for (int ma = 0; ma < 2; ma++)
#pragma unroll
        for (int nb = 0; nb < 8; nb++)
#pragma unroll
            for (int c = 0; c < 4; c++) acc[ma][nb][c] = 0.f;

    stage_load(sbase, 0, m0, n0, tid);
    CP_COMMIT();
    stage_load(sbase, 1, m0, n0, tid);
    CP_COMMIT();

    for (int s = 0; s < NSTAGES; s++) {
        if (s + 2 < NSTAGES) stage_load(sbase, s + 2, m0, n0, tid);
        CP_COMMIT();
        CP_WAIT2();
        __syncthreads();

        const uint32_t sb = sbase + (s % 3) * STG_BYTES;
        const uint32_t aHi = sb;
        const uint32_t aLo = sb + REG_BYTES;
        const uint32_t wHi = sb + 2 * REG_BYTES;
        const uint32_t wLo = sb + 3 * REG_BYTES;

#pragma unroll
        for (int kk = 0; kk < 2; kk++) {
            const uint32_t aoff = (lane & 15) * PITCH_B + (lane >> 4) * 16 + kk * 32;
            const uint32_t boff = (lane & 7) * PITCH_B + ((lane >> 3) & 1) * 16 + kk * 32;

            uint32_t ahi[2][4], alo[2][4];
            ldsm4(ahi[0], aHi + (wm + 0) * PITCH_B + aoff);
            ldsm4(ahi[1], aHi + (wm + 16) * PITCH_B + aoff);
            ldsm4(alo[0], aLo + (wm + 0) * PITCH_B + aoff);
            ldsm4(alo[1], aLo + (wm + 16) * PITCH_B + aoff);

            uint32_t whi[8][2], wlo[8][2];
#pragma unroll
            for (int nb = 0; nb < 8; nb++) {
                ldsm2(whi[nb], wHi + (wn + nb * 8) * PITCH_B + boff);
                ldsm2(wlo[nb], wLo + (wn + nb * 8) * PITCH_B + boff);
            }

#pragma unroll
            for (int ma = 0; ma < 2; ma++)
#pragma unroll
                for (int nb = 0; nb < 8; nb++) {
                    mma16816(acc[ma][nb], ahi[ma], whi[nb]);
                    mma16816(acc[ma][nb], ahi[ma], wlo[nb]);
                    mma16816(acc[ma][nb], alo[ma], whi[nb]);
                }
        }
        __syncthreads();
    }

#pragma unroll
    for (int ma = 0; ma < 2; ma++) {
        const int row = m0 + wm + ma * 16 + (lane >> 2);
#pragma unroll
        for (int nb = 0; nb < 8; nb++) {
            const int cloc = wn + nb * 8 + (lane & 3) * 2;
            const int col = n0 + cloc;
            const float b0 = s_bias[cloc], b1 = s_bias[cloc + 1];
            float2 v0 = make_float2(acc[ma][nb][0] + b0, acc[ma][nb][1] + b1);
            float2 v1 = make_float2(acc[ma][nb][2] + b0, acc[ma][nb][3] + b1);
            *reinterpret_cast<float2*>(&g_proj[(size_t)row * G4 + col]) = v0;
            *reinterpret_cast<float2*>(&g_proj[(size_t)(row + 8) * G4 + col]) = v1;
        }
    }
}

// ---------------------------------------------------------------------------
// Persistent LSTM recurrence via mma.sync bf16x3 — 256 threads (8 warps).
// Block owns 8 hidden units = 32 gate rows. W_hh bf16 hi/lo SMEM-resident.
// Per step C[32,64] = W x h; each warp owns 8 batch cols. h staged in 128-k
// chunks (cp.async double buffer). Gate transpose via 3-round shfl rotation.
// Grid barrier: atomic count + flag release + volatile poll.
// ---------------------------------------------------------------------------
#define PW       2064                    // W row pitch bytes
#define PH       272                     // h stage row pitch bytes
#define HS_BUF   (2 * 64 * PH)           // 34816
#define REC_SMEM (64 * PW + 2 * HS_BUF)  // 201728

__device__ __forceinline__ void stage_h(uint32_t smH, int sbit, int c) {
    const int kt = c * 128;
    const uint32_t dst = smH + (c & 1) * HS_BUF;
    const int tid = threadIdx.x;
#pragma unroll
    for (int t = 0; t < 8; t++) {
        const int idx = tid + t * 256;        // 0..2047
        const int half = idx >> 10;           // 0=hi 1=lo
        const int row = (idx >> 4) & 63;      // batch row
        const int kc = idx & 15;              // 16B column chunk
        const __nv_bfloat16* g =
            (half ? g_hlo[sbit] : g_hhi[sbit]) + row * HID + kt + kc * 8;
        CP_ASYNC16(dst + half * (64 * PH) + row * PH + kc * 16, g);
    }
}

__global__ __launch_bounds__(256, 1) void lstm_mma_kernel(
    const float* __restrict__ W,   // W_hh [4096,1024] fp32
    float* __restrict__ out,       // layer output fp32 (nullptr -> write bf16 A)
    float* __restrict__ hn,
    float* __restrict__ cn)
{
    extern __shared__ char sm[];
    const uint32_t smW = smem_u32(sm);
    const uint32_t smWlo = smW + 32 * PW;
    const uint32_t smH = smW + 64 * PW;

    const int tid = threadIdx.x;
    const int wid = tid >> 5;        // 0..7
    const int lane = tid & 31;
    const int blk = blockIdx.x;
    const int q = (lane >> 2) & 3;   // gate bits of lane
    const int t2 = lane >> 4;        // unit sub-index
    const int sL = lane & 3;         // batch col pair

    // Stage W_hh slice: smem row r=u*4+g  <-  W[(g*HID + blk*8 + u)][k]
    for (int r = wid; r < 32; r += 8) {
        const int u = r >> 2, g = r & 3;
        const float* src = W + ((size_t)(g * HID + blk * 8 + u)) * HID;
        __nv_bfloat16* dh = reinterpret_cast<__nv_bfloat16*>(sm + r * PW);
        __nv_bfloat16* dl = reinterpret_cast<__nv_bfloat16*>(sm + 32 * PW + r * PW);
        for (int k = lane; k < HID; k += 32) {
            float v = src[k];
            __nv_bfloat16 h = __float2bfloat16_rn(v);
            dh[k] = h;
            dl[k] = __float2bfloat16_rn(v - __bfloat162float(h));
        }
    }
    __syncthreads();

    const int bcol = wid * 8 + sL * 2 + (q & 1);   // this thread's batch col
    float cst[2] = {0.f, 0.f};

    for (int s = 0; s < SEQ; s++) {
        // Prefetch x-projection for this thread's 2 (unit,batch) combos
        float pv[2][4];
#pragma unroll
        for (int mt = 0; mt < 2; mt++) {
            const int U = mt * 4 + t2 + 2 * (q >> 1);
            const int jg = blk * 8 + U;
            const float* pb = g_proj + ((size_t)(s * BATCH + bcol)) * G4 + jg;
#pragma unroll
            for (int g = 0; g < 4; g++)
                pv[mt][g] = __ldg(&pb[g * HID]);
        }

        float acc[2][4];
#pragma unroll
        for (int mt = 0; mt < 2; mt++)
#pragma unroll
            for (int c = 0; c < 4; c++) acc[mt][c] = 0.f;

        stage_h(smH, s & 1, 0);
        CP_COMMIT();

        for (int c = 0; c < 8; c++) {
            if (c + 1 < 8) stage_h(smH, s & 1, c + 1);
            CP_COMMIT();
            CP_WAIT1();
            __syncthreads();

            const uint32_t hb = smH + (c & 1) * HS_BUF;
#pragma unroll
            for (int kk = 0; kk < 8; kk++) {
                const uint32_t aoff = (lane & 15) * PW + (lane >> 4) * 16
                                    + c * 256 + kk * 32;
                uint32_t awh[2][4], awl[2][4];
                ldsm4(awh[0], smW + aoff);
                ldsm4(awh[1], smW + 16 * PW + aoff);
                ldsm4(awl[0], smWlo + aoff);
                ldsm4(awl[1], smWlo + 16 * PW + aoff);

                const uint32_t boff = (lane & 7) * PH + ((lane >> 3) & 1) * 16
                                    + kk * 32 + wid * 8 * PH;
                uint32_t bh[2], bl[2];
                ldsm2(bh, hb + boff);
                ldsm2(bl, hb + 64 * PH + boff);

#pragma unroll
                for (int mt = 0; mt < 2; mt++) {
                    mma16816(acc[mt], awh[mt], bh);
                    mma16816(acc[mt], awh[mt], bl);
                    mma16816(acc[mt], awl[mt], bh);
                }
            }
            __syncthreads();
        }

        // Elementwise: transpose gates across lane bits 2-3, update c,h
        const int wbuf = (s + 1) & 1;
#pragma unroll
        for (int mt = 0; mt < 2; mt++) {
            const float v0 = acc[mt][0], v1 = acc[mt][1];
            const float v2 = acc[mt][2], v3 = acc[mt][3];
            float w0, w1, w2, w3;
            {
                const float r = sel4(v0, v1, v2, v3, q);
                if (q == 0) w0 = r; else if (q == 1) w1 = r;
                else if (q == 2) w2 = r; else w3 = r;
            }
#pragma unroll
            for (int j = 1; j < 4; j++) {
                const int si = (q + j) & 3;
                const int d = (q - j) & 3;
                const float send = sel4(v0, v1, v2, v3, si);
                const int src = (lane & 19) | (d << 2);
                const float r = __shfl_sync(0xffffffffu, send, src);
                if (d == 0) w0 = r; else if (d == 1) w1 = r;
                else if (d == 2) w2 = r; else w3 = r;
            }

            const float gi = sigmoidf_(w0 + pv[mt][0]);
            const float gf = sigmoidf_(w1 + pv[mt][1]);
            const float gg = tanhf_  (w2 + pv[mt][2]);
            const float go = sigmoidf_(w3 + pv[mt][3]);
            const float cnew = gf * cst[mt] + gi * gg;
            cst[mt] = cnew;
            const float hv = go * tanhf_(cnew);

            const int U = mt * 4 + t2 + 2 * (q >> 1);
            const int jg = blk * 8 + U;

            const __nv_bfloat16 hh = __float2bfloat16_rn(hv);
            const __nv_bfloat16 hl =
                __float2bfloat16_rn(hv - __bfloat162float(hh));
            g_hhi[wbuf][bcol * HID + jg] = hh;
            g_hlo[wbuf][bcol * HID + jg] = hl;
            if (out) {
                out[((size_t)s * BATCH + bcol) * HID + jg] = hv;
            } else {
                // layer 0: emit bf16 hi/lo directly as layer-1 GEMM input
                g_Ahi[((size_t)s * BATCH + bcol) * HID + jg] = hh;
                g_Alo[((size_t)s * BATCH + bcol) * HID + jg] = hl;
            }
            if (s == SEQ - 1) {
                hn[bcol * HID + jg] = hv;
                cn[bcol * HID + jg] = cnew;
            }
        }

        // Grid barrier: count + flag release + volatile poll
        __threadfence();
        __syncthreads();
        if (tid == 0) {
            const unsigned tgt = (unsigned)(s + 1);
            unsigned n = atomicAdd(&g_bar, 1u);
            if (n == tgt * gridDim.x - 1u) {
                atomicExch(&g_flag, tgt);
            } else {
                volatile unsigned* f = &g_flag;
                while (*f < tgt) { }
            }
            __threadfence();
        }
        __syncthreads();
    }
}

// ---------------------------------------------------------------------------
// Launch
// ---------------------------------------------------------------------------
extern "C" void kernel_launch(void* const* d_in, const int* in_sizes, int n_in,
                              void* d_out, int out_size)
{
    const float* x     = (const float*)d_in[0];
    const float* Wih0  = (const float*)d_in[1];
    const float* Whh0  = (const float*)d_in[2];
    const float* bih0  = (const float*)d_in[3];
    const float* bhh0  = (const float*)d_in[4];
    const float* Wih1  = (const float*)d_in[5];
    const float* Whh1  = (const float*)d_in[6];
    const float* bih1  = (const float*)d_in[7];
    const float* bhh1  = (const float*)d_in[8];

    float* out1 = (float*)d_out;
    float* hn   = out1 + (size_t)SEQ * BATCH * HID;
    float* cn   = hn + 2 * BATCH * HID;

    cudaFuncSetAttribute(mma_gemm_kernel,
                         cudaFuncAttributeMaxDynamicSharedMemorySize, GEMM_SMEM);
    cudaFuncSetAttribute(lstm_mma_kernel,
                         cudaFuncAttributeMaxDynamicSharedMemorySize, REC_SMEM);

    __nv_bfloat16 *Ahi, *Alo, *Whi, *Wlo;
    cudaGetSymbolAddress((void**)&Ahi, g_Ahi);
    cudaGetSymbolAddress((void**)&Alo, g_Alo);
    cudaGetSymbolAddress((void**)&Whi, g_Whi);
    cudaGetSymbolAddress((void**)&Wlo, g_Wlo);

    dim3 mgrid(MROWS / 128, G4 / 128);   // (256, 32), m fastest

    // ---- Layer 0 ----
    split_kernel<<<2048, 256>>>(x, Ahi, Alo, (MROWS * HID) / 4);
    split_kernel<<<512, 256>>>(Wih0, Whi, Wlo, (G4 * HID) / 4);
    zero_state_kernel<<<128, 256>>>();
    mma_gemm_kernel<<<mgrid, 256, GEMM_SMEM>>>(bih0, bhh0);
    // layer-0 recurrence writes bf16 hi/lo of out0 into g_Ahi/g_Alo directly
    lstm_mma_kernel<<<128, 256, REC_SMEM>>>(Whh0, nullptr, hn, cn);

    // ---- Layer 1 ----
    split_kernel<<<512, 256>>>(Wih1, Whi, Wlo, (G4 * HID) / 4);
    zero_state_kernel<<<128, 256>>>();
    mma_gemm_kernel<<<mgrid, 256, GEMM_SMEM>>>(bih1, bhh1);
    lstm_mma_kernel<<<128, 256, REC_SMEM>>>(Whh1, out1,
                                            hn + BATCH * HID,
                                            cn + BATCH * HID);
}

// round 6
// speedup vs baseline: 1.1485x; 1.1485x over previous
#include <cuda_runtime.h>
#include <cuda_bf16.h>
#include <cstdint>

typedef unsigned long long u64;

// ---------------------------------------------------------------------------
// Problem constants
// ---------------------------------------------------------------------------
#define SEQ   512
#define BATCH 64
#define HID   1024
#define G4    4096
#define MROWS (SEQ * BATCH)   // 32768

// ---------------------------------------------------------------------------
// Scratch (device globals)
// ---------------------------------------------------------------------------
__device__ float g_proj[(size_t)MROWS * G4];          // [T*B, 4H] x-projection
__device__ __align__(16) __nv_bfloat16 g_Ahi[(size_t)MROWS * HID];
__device__ __align__(16) __nv_bfloat16 g_Alo[(size_t)MROWS * HID];
__device__ __align__(16) __nv_bfloat16 g_Whi[(size_t)G4 * HID];
__device__ __align__(16) __nv_bfloat16 g_Wlo[(size_t)G4 * HID];
__device__ __align__(16) __nv_bfloat16 g_hh[3][BATCH * HID];   // h hi, [b][j]
__device__ __align__(16) __nv_bfloat16 g_hl[3][BATCH * HID];   // h lo, [b][j]
__device__ float g_part[2][32][4][128 * 64];                   // step-parity partials
__device__ unsigned g_cg[32];                                  // group counters
__device__ unsigned g_cs[4];                                   // slice counters

// ---------------------------------------------------------------------------
// Helpers
// ---------------------------------------------------------------------------
__device__ __forceinline__ uint32_t smem_u32(const void* p) {
    uint32_t a;
    asm("{ .reg .u64 t; cvta.to.shared.u64 t, %1; cvt.u32.u64 %0, t; }"
        : "=r"(a) : "l"(p));
    return a;
}
__device__ __forceinline__ void ldsm4(uint32_t* r, uint32_t addr) {
    asm volatile("ldmatrix.sync.aligned.m8n8.x4.shared.b16 {%0,%1,%2,%3}, [%4];"
                 : "=r"(r[0]), "=r"(r[1]), "=r"(r[2]), "=r"(r[3]) : "r"(addr));
}
__device__ __forceinline__ void ldsm2(uint32_t* r, uint32_t addr) {
    asm volatile("ldmatrix.sync.aligned.m8n8.x2.shared.b16 {%0,%1}, [%2];"
                 : "=r"(r[0]), "=r"(r[1]) : "r"(addr));
}
__device__ __forceinline__ void mma16816(float* c, const uint32_t* a, const uint32_t* b) {
    asm volatile("mma.sync.aligned.m16n8k16.row.col.f32.bf16.bf16.f32 "
                 "{%0,%1,%2,%3}, {%4,%5,%6,%7}, {%8,%9}, {%0,%1,%2,%3};"
                 : "+f"(c[0]), "+f"(c[1]), "+f"(c[2]), "+f"(c[3])
                 : "r"(a[0]), "r"(a[1]), "r"(a[2]), "r"(a[3]),
                   "r"(b[0]), "r"(b[1]));
}
#define CP_ASYNC16(sdst, gsrc) \
    asm volatile("cp.async.cg.shared.global [%0], [%1], 16;" :: "r"(sdst), "l"(gsrc))
#define CP_COMMIT() asm volatile("cp.async.commit_group;" ::: "memory")
#define CP_WAIT0()  asm volatile("cp.async.wait_group 0;" ::: "memory")
#define CP_WAIT2()  asm volatile("cp.async.wait_group 2;" ::: "memory")

__device__ __forceinline__ float sigmoidf_(float x) { return 1.0f / (1.0f + __expf(-x)); }
__device__ __forceinline__ float tanhf_(float x) { return 2.0f / (1.0f + __expf(-2.0f * x)) - 1.0f; }

// ---------------------------------------------------------------------------
// Zero h buffer 0 + counters
// ---------------------------------------------------------------------------
__global__ void zero_state_kernel() {
    int i = blockIdx.x * blockDim.x + threadIdx.x;
    if (i < 32) g_cg[i] = 0u;
    if (i >= 32 && i < 36) g_cs[i - 32] = 0u;
    const uint4 z = make_uint4(0, 0, 0, 0);
    if (i < (BATCH * HID * 2) / 16) {
        reinterpret_cast<uint4*>(&g_hh[0][0])[i] = z;
        reinterpret_cast<uint4*>(&g_hl[0][0])[i] = z;
    }
}

// ---------------------------------------------------------------------------
// fp32 -> bf16 hi/lo split
// ---------------------------------------------------------------------------
__global__ void split_kernel(const float* __restrict__ src,
                             __nv_bfloat16* __restrict__ hi,
                             __nv_bfloat16* __restrict__ lo, int n4) {
    int i = blockIdx.x * blockDim.x + threadIdx.x;
    int stride = gridDim.x * blockDim.x;
    for (; i < n4; i += stride) {
        float4 v = reinterpret_cast<const float4*>(src)[i];
        __nv_bfloat16 h[4], l[4];
        float vv[4] = {v.x, v.y, v.z, v.w};
#pragma unroll
        for (int k = 0; k < 4; k++) {
            h[k] = __float2bfloat16_rn(vv[k]);
            l[k] = __float2bfloat16_rn(vv[k] - __bfloat162float(h[k]));
        }
        reinterpret_cast<uint2*>(hi)[i] = *reinterpret_cast<uint2*>(h);
        reinterpret_cast<uint2*>(lo)[i] = *reinterpret_cast<uint2*>(l);
    }
}

// ---------------------------------------------------------------------------
// bf16x3 GEMM via mma.sync, 3-stage cp.async ring (validated).
// ---------------------------------------------------------------------------
#define KSTG       32
#define NSTAGES    (HID / KSTG)
#define PITCH_B    80
#define REG_BYTES  (128 * PITCH_B)
#define STG_BYTES  (4 * REG_BYTES)
#define GEMM_SMEM  (3 * STG_BYTES)

__device__ __forceinline__ void stage_load(uint32_t sbase, int s, int m0, int n0,
                                           int tid) {
    const int kt = s * KSTG;
    const uint32_t dst = sbase + (s % 3) * STG_BYTES;
#pragma unroll
    for (int r = 0; r < 4; r++) {
        const __nv_bfloat16* src =
            (r == 0) ? g_Ahi : (r == 1) ? g_Alo : (r == 2) ? g_Whi : g_Wlo;
        const int rb = (r < 2) ? m0 : n0;
#pragma unroll
        for (int j = 0; j < 2; j++) {
            const int chunk = tid + j * 256;
            const int row = chunk >> 2;
            const int kc = chunk & 3;
            const void* g = src + (size_t)(rb + row) * HID + kt + kc * 8;
            const uint32_t sd = dst + r * REG_BYTES + row * PITCH_B + kc * 16;
            CP_ASYNC16(sd, g);
        }
    }
}

__global__ __launch_bounds__(256, 1) void mma_gemm_kernel(
    const float* __restrict__ bias1, const float* __restrict__ bias2)
{
    extern __shared__ char dsm[];
    __shared__ float s_bias[128];

    const int tid = threadIdx.x;
    const int wid = tid >> 5;
    const int lane = tid & 31;
    const int m0 = blockIdx.x * 128;
    const int n0 = blockIdx.y * 128;
    const int wm = (wid & 3) * 32;
    const int wn = (wid >> 2) * 64;

    const uint32_t sbase = smem_u32(dsm);

    if (tid < 128) s_bias[tid] = bias1[n0 + tid] + bias2[n0 + tid];

    float acc[2][8][4];
#pragma unroll
    for (int ma = 0; ma < 2; ma++)
#pragma unroll
        for (int nb = 0; nb < 8; nb++)
#pragma unroll
            for (int c = 0; c < 4; c++) acc[ma][nb][c] = 0.f;

    stage_load(sbase, 0, m0, n0, tid);
    CP_COMMIT();
    stage_load(sbase, 1, m0, n0, tid);
    CP_COMMIT();

    for (int s = 0; s < NSTAGES; s++) {
        if (s + 2 < NSTAGES) stage_load(sbase, s + 2, m0, n0, tid);
        CP_COMMIT();
        CP_WAIT2();
        __syncthreads();

        const uint32_t sb = sbase + (s % 3) * STG_BYTES;
        const uint32_t aHi = sb;
        const uint32_t aLo = sb + REG_BYTES;
        const uint32_t wHi = sb + 2 * REG_BYTES;
        const uint32_t wLo = sb + 3 * REG_BYTES;

#pragma unroll
        for (int kk = 0; kk < 2; kk++) {
            const uint32_t aoff = (lane & 15) * PITCH_B + (lane >> 4) * 16 + kk * 32;
            const uint32_t boff = (lane & 7) * PITCH_B + ((lane >> 3) & 1) * 16 + kk * 32;

            uint32_t ahi[2][4], alo[2][4];
            ldsm4(ahi[0], aHi + (wm + 0) * PITCH_B + aoff);
            ldsm4(ahi[1], aHi + (wm + 16) * PITCH_B + aoff);
            ldsm4(alo[0], aLo + (wm + 0) * PITCH_B + aoff);
            ldsm4(alo[1], aLo + (wm + 16) * PITCH_B + aoff);

            uint32_t whi[8][2], wlo[8][2];
#pragma unroll
            for (int nb = 0; nb < 8; nb++) {
                ldsm2(whi[nb], wHi + (wn + nb * 8) * PITCH_B + boff);
                ldsm2(wlo[nb], wLo + (wn + nb * 8) * PITCH_B + boff);
            }

#pragma unroll
            for (int ma = 0; ma < 2; ma++)
#pragma unroll
                for (int nb = 0; nb < 8; nb++) {
                    mma16816(acc[ma][nb], ahi[ma], whi[nb]);
                    mma16816(acc[ma][nb], ahi[ma], wlo[nb]);
                    mma16816(acc[ma][nb], alo[ma], whi[nb]);
                }
        }
        __syncthreads();
    }

#pragma unroll
    for (int ma = 0; ma < 2; ma++) {
        const int row = m0 + wm + ma * 16 + (lane >> 2);
#pragma unroll
        for (int nb = 0; nb < 8; nb++) {
            const int cloc = wn + nb * 8 + (lane & 3) * 2;
            const int col = n0 + cloc;
            const float b0 = s_bias[cloc], b1 = s_bias[cloc + 1];
            float2 v0 = make_float2(acc[ma][nb][0] + b0, acc[ma][nb][1] + b1);
            float2 v1 = make_float2(acc[ma][nb][2] + b0, acc[ma][nb][3] + b1);
            *reinterpret_cast<float2*>(&g_proj[(size_t)row * G4 + col]) = v0;
            *reinterpret_cast<float2*>(&g_proj[(size_t)(row + 8) * G4 + col]) = v1;
        }
    }
}

// ---------------------------------------------------------------------------
// Persistent LSTM recurrence — split-K dataflow version.
// 128 blocks = 32 groups x 4 k-slices. Block (g,r): 32 units (128 gate rows),
// k in [256r, 256r+256). W slice bf16 hi/lo SMEM-resident. Per step:
//   MMA partial C[128,64] -> global partial (parity buffer) -> group counter
//   -> reduce own 8-unit quarter -> elementwise -> h write (triple buffer)
//   -> slice counter. No full grid barrier.
// ---------------------------------------------------------------------------
#define KSL      256
#define RPW      528                       // smem row pitch (256*2+16)
#define REC_SMEM (RPW * (256 + 128))       // W hi/lo 256 rows + h hi/lo 128 rows

__global__ __launch_bounds__(256, 1) void lstm_mma_kernel(
    const float* __restrict__ W,   // W_hh [4096,1024] fp32
    float* __restrict__ out,       // fp32 out (nullptr -> emit bf16 A hi/lo)
    float* __restrict__ hn,
    float* __restrict__ cn)
{
    extern __shared__ char sm[];
    const uint32_t smW = smem_u32(sm);          // W hi rows [0,128), lo [128,256)
    const uint32_t smH = smW + 256 * RPW;       // h hi rows [0,64), lo [64,128)
    float* smHv = reinterpret_cast<float*>(sm + 256 * RPW);  // reuse post-MMA

    const int tid = threadIdx.x;
    const int wid = tid >> 5;
    const int lane = tid & 31;
    const int grp = blockIdx.x >> 2;     // 0..31
    const int r   = blockIdx.x & 3;      // k-slice
    const int wr  = wid & 3;             // warp row group (4)
    const int wc  = wid >> 2;            // warp col group (2)

    // ---- Stage W_hh slice into SMEM (hi/lo), rows = u*4 + gate ----
    {
        const int row = tid >> 1;            // 0..127
        const int half = tid & 1;
        const int u = row >> 2, gg = row & 3;
        const float* src = W + ((size_t)(gg * HID + grp * 32 + u)) * HID + r * KSL
                         + half * 128;
        __nv_bfloat16* dh = reinterpret_cast<__nv_bfloat16*>(sm + row * RPW) + half * 128;
        __nv_bfloat16* dl = reinterpret_cast<__nv_bfloat16*>(sm + (128 + row) * RPW) + half * 128;
        for (int k = 0; k < 128; k++) {
            float v = src[k];
            __nv_bfloat16 h = __float2bfloat16_rn(v);
            dh[k] = h;
            dl[k] = __float2bfloat16_rn(v - __bfloat162float(h));
        }
    }
    __syncthreads();

    const int bq = tid & 63;             // batch col for reduce phase
    const int uq = tid >> 6;             // unit quarter base
    float cst[2] = {0.f, 0.f};

    for (int s = 0; s < SEQ; s++) {
        const int cb = s % 3;
        const int nb3 = (s + 1) % 3;
        const int pb = s & 1;

        // ---- Wait for h of this step's k-slice ----
        if (s > 0) {
            if (tid == 0) {
                volatile unsigned* c = &g_cs[r];
                const unsigned tgt = 32u * (unsigned)s;
                while (*c < tgt) __nanosleep(64);
            }
            __syncthreads();
            __threadfence();
        }

        // ---- Stage h slice (64 rows x 256 k, hi+lo) via cp.async ----
#pragma unroll
        for (int t = 0; t < 16; t++) {
            const int idx = tid + t * 256;       // 0..4095
            const int arr = idx >> 11;           // 0=hi 1=lo
            const int rem = idx & 2047;
            const int row = rem >> 5;            // batch row
            const int kc = rem & 31;             // 16B chunk
            const __nv_bfloat16* g =
                (arr ? g_hl[cb] : g_hh[cb]) + row * HID + r * KSL + kc * 8;
            CP_ASYNC16(smH + arr * (64 * RPW) + row * RPW + kc * 16, g);
        }
        CP_COMMIT();

        // Prefetch x-projection (independent of h/partials)
        float pv[2][4];
#pragma unroll
        for (int p = 0; p < 2; p++) {
            const int u_local = r * 8 + uq + p * 4;
            const int j = grp * 32 + u_local;
            const float* pp = g_proj + ((size_t)(s * BATCH + bq)) * G4 + j;
#pragma unroll
            for (int gg = 0; gg < 4; gg++)
                pv[p][gg] = __ldg(&pp[gg * HID]);
        }

        CP_WAIT0();
        __syncthreads();

        // ---- MMA: C[128,64] partial over k-slice, bf16x3 ----
        float acc[2][4][4];
#pragma unroll
        for (int mt = 0; mt < 2; mt++)
#pragma unroll
            for (int nt = 0; nt < 4; nt++)
#pragma unroll
                for (int c = 0; c < 4; c++) acc[mt][nt][c] = 0.f;

#pragma unroll
        for (int kk = 0; kk < 16; kk++) {
            const uint32_t aoff = (lane & 15) * RPW + (lane >> 4) * 16 + kk * 32;
            const uint32_t boff = (lane & 7) * RPW + ((lane >> 3) & 1) * 16 + kk * 32;

            uint32_t awh[2][4], awl[2][4];
#pragma unroll
            for (int mt = 0; mt < 2; mt++) {
                const uint32_t ar = (wr * 32 + mt * 16) * RPW;
                ldsm4(awh[mt], smW + ar + aoff);
                ldsm4(awl[mt], smW + 128 * RPW + ar + aoff);
            }
            uint32_t bh[4][2], bl[4][2];
#pragma unroll
            for (int nt = 0; nt < 4; nt++) {
                const uint32_t br = (wc * 32 + nt * 8) * RPW;
                ldsm2(bh[nt], smH + br + boff);
                ldsm2(bl[nt], smH + 64 * RPW + br + boff);
            }
#pragma unroll
            for (int mt = 0; mt < 2; mt++)
#pragma unroll
                for (int nt = 0; nt < 4; nt++) {
                    mma16816(acc[mt][nt], awh[mt], bh[nt]);
                    mma16816(acc[mt][nt], awh[mt], bl[nt]);
                    mma16816(acc[mt][nt], awl[mt], bh[nt]);
                }
        }
        __syncthreads();   // h smem free; smHv reuse below

        // ---- Write partial to global (parity buffer) ----
        {
            float* pp = &g_part[pb][grp][r][0];
#pragma unroll
            for (int mt = 0; mt < 2; mt++) {
                const int row = wr * 32 + mt * 16 + (lane >> 2);
#pragma unroll
                for (int nt = 0; nt < 4; nt++) {
                    const int col = wc * 32 + nt * 8 + (lane & 3) * 2;
                    *reinterpret_cast<float2*>(&pp[row * 64 + col]) =
                        make_float2(acc[mt][nt][0], acc[mt][nt][1]);
                    *reinterpret_cast<float2*>(&pp[(row + 8) * 64 + col]) =
                        make_float2(acc[mt][nt][2], acc[mt][nt][3]);
                }
            }
        }
        __threadfence();
        __syncthreads();
        if (tid == 0) {
            atomicAdd(&g_cg[grp], 1u);
            volatile unsigned* c = &g_cg[grp];
            const unsigned tgt = 4u * (unsigned)(s + 1);
            while (*c < tgt) __nanosleep(32);
        }
        __syncthreads();
        __threadfence();

        // ---- Reduce own 8-unit quarter + elementwise ----
        const float* p0 = &g_part[pb][grp][0][0];
        const float* p1 = &g_part[pb][grp][1][0];
        const float* p2 = &g_part[pb][grp][2][0];
        const float* p3 = &g_part[pb][grp][3][0];
#pragma unroll
        for (int p = 0; p < 2; p++) {
            const int u_idx = uq + p * 4;
            const int u_local = r * 8 + u_idx;
            const int j = grp * 32 + u_local;
            float gate[4];
#pragma unroll
            for (int gg = 0; gg < 4; gg++) {
                const int off = (u_local * 4 + gg) * 64 + bq;
                gate[gg] = __ldcg(&p0[off]) + __ldcg(&p1[off])
                         + __ldcg(&p2[off]) + __ldcg(&p3[off]) + pv[p][gg];
            }
            const float gi = sigmoidf_(gate[0]);
            const float gf = sigmoidf_(gate[1]);
            const float gG = tanhf_(gate[2]);
            const float go = sigmoidf_(gate[3]);
            const float cnew = gf * cst[p] + gi * gG;
            cst[p] = cnew;
            const float hv = go * tanhf_(cnew);
            smHv[u_idx * 64 + bq] = hv;
            if (s == SEQ - 1) {
                hn[bq * HID + j] = hv;
                cn[bq * HID + j] = cnew;
            }
        }
        __syncthreads();

        // ---- Vectorized h / out writes (transposed through SMEM) ----
        {
            const int j0 = grp * 32 + r * 8;
            const int role = tid >> 6;       // 0:hh 1:hl 2:out/Ahi 3:-/Alo
            const int b = tid & 63;
            float hv8[8];
#pragma unroll
            for (int u = 0; u < 8; u++) hv8[u] = smHv[u * 64 + b];

            if (role == 0) {
                __nv_bfloat16 h8[8];
#pragma unroll
                for (int u = 0; u < 8; u++) h8[u] = __float2bfloat16_rn(hv8[u]);
                *reinterpret_cast<uint4*>(&g_hh[nb3][b * HID + j0]) =
                    *reinterpret_cast<uint4*>(h8);
            } else if (role == 1) {
                __nv_bfloat16 l8[8];
#pragma unroll
                for (int u = 0; u < 8; u++) {
                    __nv_bfloat16 h = __float2bfloat16_rn(hv8[u]);
                    l8[u] = __float2bfloat16_rn(hv8[u] - __bfloat162float(h));
                }
                *reinterpret_cast<uint4*>(&g_hl[nb3][b * HID + j0]) =
                    *reinterpret_cast<uint4*>(l8);
            } else if (role == 2) {
                if (out) {
                    float* o = &out[((size_t)(s * BATCH + b)) * HID + j0];
                    *reinterpret_cast<float4*>(o) =
                        make_float4(hv8[0], hv8[1], hv8[2], hv8[3]);
                    *reinterpret_cast<float4*>(o + 4) =
                        make_float4(hv8[4], hv8[5], hv8[6], hv8[7]);
                } else {
                    __nv_bfloat16 h8[8];
#pragma unroll
                    for (int u = 0; u < 8; u++) h8[u] = __float2bfloat16_rn(hv8[u]);
                    *reinterpret_cast<uint4*>(
                        &g_Ahi[((size_t)(s * BATCH + b)) * HID + j0]) =
                        *reinterpret_cast<uint4*>(h8);
                }
            } else {
                if (!out) {
                    __nv_bfloat16 l8[8];
#pragma unroll
                    for (int u = 0; u < 8; u++) {
                        __nv_bfloat16 h = __float2bfloat16_rn(hv8[u]);
                        l8[u] = __float2bfloat16_rn(hv8[u] - __bfloat162float(h));
                    }
                    *reinterpret_cast<uint4*>(
                        &g_Alo[((size_t)(s * BATCH + b)) * HID + j0]) =
                        *reinterpret_cast<uint4*>(l8);
                }
            }
        }
        __threadfence();
        __syncthreads();
        if (tid == 0) atomicAdd(&g_cs[grp >> 3], 1u);
    }
}

// ---------------------------------------------------------------------------
// Launch
// ---------------------------------------------------------------------------
extern "C" void kernel_launch(void* const* d_in, const int* in_sizes, int n_in,
                              void* d_out, int out_size)
{
    const float* x     = (const float*)d_in[0];
    const float* Wih0  = (const float*)d_in[1];
    const float* Whh0  = (const float*)d_in[2];
    const float* bih0  = (const float*)d_in[3];
    const float* bhh0  = (const float*)d_in[4];
    const float* Wih1  = (const float*)d_in[5];
    const float* Whh1  = (const float*)d_in[6];
    const float* bih1  = (const float*)d_in[7];
    const float* bhh1  = (const float*)d_in[8];

    float* out1 = (float*)d_out;
    float* hn   = out1 + (size_t)SEQ * BATCH * HID;
    float* cn   = hn + 2 * BATCH * HID;

    cudaFuncSetAttribute(mma_gemm_kernel,
                         cudaFuncAttributeMaxDynamicSharedMemorySize, GEMM_SMEM);
    cudaFuncSetAttribute(lstm_mma_kernel,
                         cudaFuncAttributeMaxDynamicSharedMemorySize, REC_SMEM);

    __nv_bfloat16 *Ahi, *Alo, *Whi, *Wlo;
    cudaGetSymbolAddress((void**)&Ahi, g_Ahi);
    cudaGetSymbolAddress((void**)&Alo, g_Alo);
    cudaGetSymbolAddress((void**)&Whi, g_Whi);
    cudaGetSymbolAddress((void**)&Wlo, g_Wlo);

    dim3 mgrid(MROWS / 128, G4 / 128);

    // ---- Layer 0 ----
    split_kernel<<<2048, 256>>>(x, Ahi, Alo, (MROWS * HID) / 4);
    split_kernel<<<512, 256>>>(Wih0, Whi, Wlo, (G4 * HID) / 4);
    zero_state_kernel<<<64, 256>>>();
    mma_gemm_kernel<<<mgrid, 256, GEMM_SMEM>>>(bih0, bhh0);
    lstm_mma_kernel<<<128, 256, REC_SMEM>>>(Whh0, nullptr, hn, cn);

    // ---- Layer 1 ----
    split_kernel<<<512, 256>>>(Wih1, Whi, Wlo, (G4 * HID) / 4);
    zero_state_kernel<<<64, 256>>>();
    mma_gemm_kernel<<<mgrid, 256, GEMM_SMEM>>>(bih1, bhh1);
    lstm_mma_kernel<<<128, 256, REC_SMEM>>>(Whh1, out1,
                                            hn + BATCH * HID,
                                            cn + BATCH * HID);
}

// round 7
// speedup vs baseline: 1.2780x; 1.1127x over previous
#include <cuda_runtime.h>
#include <cuda_bf16.h>
#include <cstdint>

typedef unsigned long long u64;

// ---------------------------------------------------------------------------
// Problem constants
// ---------------------------------------------------------------------------
#define SEQ   512
#define BATCH 64
#define HID   1024
#define G4    4096
#define MROWS (SEQ * BATCH)   // 32768

// ---------------------------------------------------------------------------
// Scratch (device globals)
// ---------------------------------------------------------------------------
__device__ float g_proj[(size_t)MROWS * G4];          // [T*B, 4H] x-projection
__device__ __align__(16) __nv_bfloat16 g_Ahi[(size_t)MROWS * HID];
__device__ __align__(16) __nv_bfloat16 g_Alo[(size_t)MROWS * HID];
__device__ __align__(16) __nv_bfloat16 g_Whi[(size_t)G4 * HID];
__device__ __align__(16) __nv_bfloat16 g_Wlo[(size_t)G4 * HID];
__device__ __align__(16) __nv_bfloat16 g_hh[3][BATCH * HID];   // h hi, [b][j]
__device__ __align__(16) __nv_bfloat16 g_hl[3][BATCH * HID];   // h lo, [b][j]
__device__ unsigned g_done[32];                                // per-group h publish

// ---------------------------------------------------------------------------
// Helpers
// ---------------------------------------------------------------------------
__device__ __forceinline__ uint32_t smem_u32(const void* p) {
    uint32_t a;
    asm("{ .reg .u64 t; cvta.to.shared.u64 t, %1; cvt.u32.u64 %0, t; }"
        : "=r"(a) : "l"(p));
    return a;
}
__device__ __forceinline__ void ldsm4(uint32_t* r, uint32_t addr) {
    asm volatile("ldmatrix.sync.aligned.m8n8.x4.shared.b16 {%0,%1,%2,%3}, [%4];"
                 : "=r"(r[0]), "=r"(r[1]), "=r"(r[2]), "=r"(r[3]) : "r"(addr));
}
__device__ __forceinline__ void ldsm2(uint32_t* r, uint32_t addr) {
    asm volatile("ldmatrix.sync.aligned.m8n8.x2.shared.b16 {%0,%1}, [%2];"
                 : "=r"(r[0]), "=r"(r[1]) : "r"(addr));
}
__device__ __forceinline__ void mma16816(float* c, const uint32_t* a, const uint32_t* b) {
    asm volatile("mma.sync.aligned.m16n8k16.row.col.f32.bf16.bf16.f32 "
                 "{%0,%1,%2,%3}, {%4,%5,%6,%7}, {%8,%9}, {%0,%1,%2,%3};"
                 : "+f"(c[0]), "+f"(c[1]), "+f"(c[2]), "+f"(c[3])
                 : "r"(a[0]), "r"(a[1]), "r"(a[2]), "r"(a[3]),
                   "r"(b[0]), "r"(b[1]));
}
#define CP_ASYNC16(sdst, gsrc) \
    asm volatile("cp.async.cg.shared.global [%0], [%1], 16;" :: "r"(sdst), "l"(gsrc))
#define CP_COMMIT() asm volatile("cp.async.commit_group;" ::: "memory")
#define CP_WAIT0()  asm volatile("cp.async.wait_group 0;" ::: "memory")
#define CP_WAIT2()  asm volatile("cp.async.wait_group 2;" ::: "memory")

#define CLUSTER_ARRIVE() asm volatile("barrier.cluster.arrive.aligned;" ::: "memory")
#define CLUSTER_WAIT()   asm volatile("barrier.cluster.wait.aligned;" ::: "memory")

__device__ __forceinline__ uint32_t mapa_rank(uint32_t addr, int rank) {
    uint32_t r;
    asm("mapa.shared::cluster.u32 %0, %1, %2;" : "=r"(r) : "r"(addr), "r"(rank));
    return r;
}
__device__ __forceinline__ void sts_cluster64(uint32_t addr, float a, float b) {
    u64 v; asm("mov.b64 %0, {%1,%2};" : "=l"(v) : "f"(a), "f"(b));
    asm volatile("st.shared::cluster.b64 [%0], %1;" :: "r"(addr), "l"(v) : "memory");
}

__device__ __forceinline__ float sigmoidf_(float x) { return 1.0f / (1.0f + __expf(-x)); }
__device__ __forceinline__ float tanhf_(float x) { return 2.0f / (1.0f + __expf(-2.0f * x)) - 1.0f; }

// ---------------------------------------------------------------------------
// Zero h buffer 0 + counters
// ---------------------------------------------------------------------------
__global__ void zero_state_kernel() {
    int i = blockIdx.x * blockDim.x + threadIdx.x;
    if (i < 32) g_done[i] = 0u;
    const uint4 z = make_uint4(0, 0, 0, 0);
    if (i < (BATCH * HID * 2) / 16) {
        reinterpret_cast<uint4*>(&g_hh[0][0])[i] = z;
        reinterpret_cast<uint4*>(&g_hl[0][0])[i] = z;
    }
}

// ---------------------------------------------------------------------------
// fp32 -> bf16 hi/lo split
// ---------------------------------------------------------------------------
__global__ void split_kernel(const float* __restrict__ src,
                             __nv_bfloat16* __restrict__ hi,
                             __nv_bfloat16* __restrict__ lo, int n4) {
    int i = blockIdx.x * blockDim.x + threadIdx.x;
    int stride = gridDim.x * blockDim.x;
    for (; i < n4; i += stride) {
        float4 v = reinterpret_cast<const float4*>(src)[i];
        __nv_bfloat16 h[4], l[4];
        float vv[4] = {v.x, v.y, v.z, v.w};
#pragma unroll
        for (int k = 0; k < 4; k++) {
            h[k] = __float2bfloat16_rn(vv[k]);
            l[k] = __float2bfloat16_rn(vv[k] - __bfloat162float(h[k]));
        }
        reinterpret_cast<uint2*>(hi)[i] = *reinterpret_cast<uint2*>(h);
        reinterpret_cast<uint2*>(lo)[i] = *reinterpret_cast<uint2*>(l);
    }
}

// ---------------------------------------------------------------------------
// bf16x3 GEMM via mma.sync, 3-stage cp.async ring (validated).
// ---------------------------------------------------------------------------
#define KSTG       32
#define NSTAGES    (HID / KSTG)
#define PITCH_B    80
#define REG_BYTES  (128 * PITCH_B)
#define STG_BYTES  (4 * REG_BYTES)
#define GEMM_SMEM  (3 * STG_BYTES)

__device__ __forceinline__ void stage_load(uint32_t sbase, int s, int m0, int n0,
                                           int tid) {
    const int kt = s * KSTG;
    const uint32_t dst = sbase + (s % 3) * STG_BYTES;
#pragma unroll
    for (int r = 0; r < 4; r++) {
        const __nv_bfloat16* src =
            (r == 0) ? g_Ahi : (r == 1) ? g_Alo : (r == 2) ? g_Whi : g_Wlo;
        const int rb = (r < 2) ? m0 : n0;
#pragma unroll
        for (int j = 0; j < 2; j++) {
            const int chunk = tid + j * 256;
            const int row = chunk >> 2;
            const int kc = chunk & 3;
            const void* g = src + (size_t)(rb + row) * HID + kt + kc * 8;
            const uint32_t sd = dst + r * REG_BYTES + row * PITCH_B + kc * 16;
            CP_ASYNC16(sd, g);
        }
    }
}

__global__ __launch_bounds__(256, 1) void mma_gemm_kernel(
    const float* __restrict__ bias1, const float* __restrict__ bias2)
{
    extern __shared__ char dsm[];
    __shared__ float s_bias[128];

    const int tid = threadIdx.x;
    const int wid = tid >> 5;
    const int lane = tid & 31;
    const int m0 = blockIdx.x * 128;
    const int n0 = blockIdx.y * 128;
    const int wm = (wid & 3) * 32;
    const int wn = (wid >> 2) * 64;

    const uint32_t sbase = smem_u32(dsm);

    if (tid < 128) s_bias[tid] = bias1[n0 + tid] + bias2[n0 + tid];

    float acc[2][8][4];
#pragma unroll
    for (int ma = 0; ma < 2; ma++)
#pragma unroll
        for (int nb = 0; nb < 8; nb++)
#pragma unroll
            for (int c = 0; c < 4; c++) acc[ma][nb][c] = 0.f;

    stage_load(sbase, 0, m0, n0, tid);
    CP_COMMIT();
    stage_load(sbase, 1, m0, n0, tid);
    CP_COMMIT();

    for (int s = 0; s < NSTAGES; s++) {
        if (s + 2 < NSTAGES) stage_load(sbase, s + 2, m0, n0, tid);
        CP_COMMIT();
        CP_WAIT2();
        __syncthreads();

        const uint32_t sb = sbase + (s % 3) * STG_BYTES;
        const uint32_t aHi = sb;
        const uint32_t aLo = sb + REG_BYTES;
        const uint32_t wHi = sb + 2 * REG_BYTES;
        const uint32_t wLo = sb + 3 * REG_BYTES;

#pragma unroll
        for (int kk = 0; kk < 2; kk++) {
            const uint32_t aoff = (lane & 15) * PITCH_B + (lane >> 4) * 16 + kk * 32;
            const uint32_t boff = (lane & 7) * PITCH_B + ((lane >> 3) & 1) * 16 + kk * 32;

            uint32_t ahi[2][4], alo[2][4];
            ldsm4(ahi[0], aHi + (wm + 0) * PITCH_B + aoff);
            ldsm4(ahi[1], aHi + (wm + 16) * PITCH_B + aoff);
            ldsm4(alo[0], aLo + (wm + 0) * PITCH_B + aoff);
            ldsm4(alo[1], aLo + (wm + 16) * PITCH_B + aoff);

            uint32_t whi[8][2], wlo[8][2];
#pragma unroll
            for (int nb = 0; nb < 8; nb++) {
                ldsm2(whi[nb], wHi + (wn + nb * 8) * PITCH_B + boff);
                ldsm2(wlo[nb], wLo + (wn + nb * 8) * PITCH_B + boff);
            }

#pragma unroll
            for (int ma = 0; ma < 2; ma++)
#pragma unroll
                for (int nb = 0; nb < 8; nb++) {
                    mma16816(acc[ma][nb], ahi[ma], whi[nb]);
                    mma16816(acc[ma][nb], ahi[ma], wlo[nb]);
                    mma16816(acc[ma][nb], alo[ma], whi[nb]);
                }
        }
        __syncthreads();
    }

#pragma unroll
    for (int ma = 0; ma < 2; ma++) {
        const int row = m0 + wm + ma * 16 + (lane >> 2);
#pragma unroll
        for (int nb = 0; nb < 8; nb++) {
            const int cloc = wn + nb * 8 + (lane & 3) * 2;
            const int col = n0 + cloc;
            const float b0 = s_bias[cloc], b1 = s_bias[cloc + 1];
            float2 v0 = make_float2(acc[ma][nb][0] + b0, acc[ma][nb][1] + b1);
            float2 v1 = make_float2(acc[ma][nb][2] + b0, acc[ma][nb][3] + b1);
            *reinterpret_cast<float2*>(&g_proj[(size_t)row * G4 + col]) = v0;
            *reinterpret_cast<float2*>(&g_proj[(size_t)(row + 8) * G4 + col]) = v1;
        }
    }
}

// ---------------------------------------------------------------------------
// Persistent LSTM recurrence — split-K + cluster DSMEM partial exchange.
// 128 blocks = 32 groups x 4 k-slices; cluster (4,1,1) = one group.
// Block (g,r): 32 units (128 gate rows), k in [256r, 256r+256). Per step:
//   MMA partial -> cluster barrier -> DSMEM quarter exchange -> cluster
//   barrier -> local LDS reduce -> elementwise -> h publish (triple buffer)
//   -> per-group release counter. h wait: parallel acquire polls.
// ---------------------------------------------------------------------------
#define KSL      256
#define RPW      528
#define REC_SMEM (RPW * (256 + 128))       // 202752

__global__ __launch_bounds__(256, 1) __cluster_dims__(4, 1, 1)
void lstm_mma_kernel(
    const float* __restrict__ W,   // W_hh [4096,1024] fp32
    float* __restrict__ out,       // fp32 out (nullptr -> emit bf16 A hi/lo)
    float* __restrict__ hn,
    float* __restrict__ cn)
{
    extern __shared__ char sm[];
    const uint32_t smW = smem_u32(sm);          // W hi rows [0,128), lo [128,256)
    const uint32_t smH = smW + 256 * RPW;       // h staging / exchange scratch
    float* slots = reinterpret_cast<float*>(sm + 256 * RPW);          // 4 x 8KB
    float* smHv  = reinterpret_cast<float*>(sm + 256 * RPW + 32768);  // 2KB

    const int tid = threadIdx.x;
    const int wid = tid >> 5;
    const int lane = tid & 31;
    const int grp = blockIdx.x >> 2;     // 0..31
    const int r   = blockIdx.x & 3;      // k-slice == cluster rank
    const int wr  = wid & 3;             // warp row group
    const int wc  = wid >> 2;            // warp col group

    // ---- Stage W_hh slice into SMEM (hi/lo), rows = u*4 + gate ----
    {
        const int row = tid >> 1;            // 0..127
        const int half = tid & 1;
        const int u = row >> 2, gg = row & 3;
        const float* src = W + ((size_t)(gg * HID + grp * 32 + u)) * HID + r * KSL
                         + half * 128;
        __nv_bfloat16* dh = reinterpret_cast<__nv_bfloat16*>(sm + row * RPW) + half * 128;
        __nv_bfloat16* dl = reinterpret_cast<__nv_bfloat16*>(sm + (128 + row) * RPW) + half * 128;
        for (int k = 0; k < 128; k++) {
            float v = src[k];
            __nv_bfloat16 h = __float2bfloat16_rn(v);
            dh[k] = h;
            dl[k] = __float2bfloat16_rn(v - __bfloat162float(h));
        }
    }
    __syncthreads();

    const int bq = tid & 63;             // batch col for reduce phase
    const int uq = tid >> 6;             // unit quarter base
    float cst[2] = {0.f, 0.f};

    for (int s = 0; s < SEQ; s++) {
        const int cb = s % 3;
        const int nb3 = (s + 1) % 3;

        // ---- Prefetch x-projection (independent of h) ----
        float pv[2][4];
#pragma unroll
        for (int p = 0; p < 2; p++) {
            const int u_local = r * 8 + uq + p * 4;
            const int j = grp * 32 + u_local;
            const float* pp = g_proj + ((size_t)(s * BATCH + bq)) * G4 + j;
#pragma unroll
            for (int gg = 0; gg < 4; gg++)
                pv[p][gg] = __ldg(&pp[gg * HID]);
        }

        // ---- Wait for the 8 source groups' h of step s-1 (acquire) ----
        if (s > 0) {
            if (tid < 8) {
                const unsigned tgt = 4u * (unsigned)s;
                const unsigned* ad = &g_done[8 * r + tid];
                unsigned v;
                for (;;) {
                    asm volatile("ld.acquire.gpu.global.u32 %0, [%1];"
                                 : "=r"(v) : "l"(ad));
                    if (v >= tgt) break;
                    __nanosleep(32);
                }
            }
            __syncthreads();
        }

        // ---- Stage h slice (64 rows x 256 k, hi+lo) via cp.async ----
#pragma unroll
        for (int t = 0; t < 16; t++) {
            const int idx = tid + t * 256;       // 0..4095
            const int arr = idx >> 11;           // 0=hi 1=lo
            const int rem = idx & 2047;
            const int row = rem >> 5;            // batch row
            const int kc = rem & 31;             // 16B chunk
            const __nv_bfloat16* g =
                (arr ? g_hl[cb] : g_hh[cb]) + row * HID + r * KSL + kc * 8;
            CP_ASYNC16(smH + arr * (64 * RPW) + row * RPW + kc * 16, g);
        }
        CP_COMMIT();
        CP_WAIT0();
        __syncthreads();

        // ---- MMA: C[128,64] partial over k-slice, bf16x3 ----
        float acc[2][4][4];
#pragma unroll
        for (int mt = 0; mt < 2; mt++)
#pragma unroll
            for (int nt = 0; nt < 4; nt++)
#pragma unroll
                for (int c = 0; c < 4; c++) acc[mt][nt][c] = 0.f;

#pragma unroll
        for (int kk = 0; kk < 16; kk++) {
            const uint32_t aoff = (lane & 15) * RPW + (lane >> 4) * 16 + kk * 32;
            const uint32_t boff = (lane & 7) * RPW + ((lane >> 3) & 1) * 16 + kk * 32;

            uint32_t awh[2][4], awl[2][4];
#pragma unroll
            for (int mt = 0; mt < 2; mt++) {
                const uint32_t ar = (wr * 32 + mt * 16) * RPW;
                ldsm4(awh[mt], smW + ar + aoff);
                ldsm4(awl[mt], smW + 128 * RPW + ar + aoff);
            }
            uint32_t bh[4][2], bl[4][2];
#pragma unroll
            for (int nt = 0; nt < 4; nt++) {
                const uint32_t br = (wc * 32 + nt * 8) * RPW;
                ldsm2(bh[nt], smH + br + boff);
                ldsm2(bl[nt], smH + 64 * RPW + br + boff);
            }
#pragma unroll
            for (int mt = 0; mt < 2; mt++)
#pragma unroll
                for (int nt = 0; nt < 4; nt++) {
                    mma16816(acc[mt][nt], awh[mt], bh[nt]);
                    mma16816(acc[mt][nt], awh[mt], bl[nt]);
                    mma16816(acc[mt][nt], awl[mt], bh[nt]);
                }
        }

        // ---- Cluster barrier #1: all MMAs done, h smem now scratch ----
        CLUSTER_ARRIVE();
        CLUSTER_WAIT();

        // ---- DSMEM exchange: warp row-group wr -> rank wr, slot r ----
        {
            const uint32_t dst = mapa_rank(smH + (uint32_t)(r * 8192), wr);
#pragma unroll
            for (int mt = 0; mt < 2; mt++) {
                const int rl = mt * 16 + (lane >> 2);     // local row in quarter
#pragma unroll
                for (int nt = 0; nt < 4; nt++) {
                    const int col = wc * 32 + nt * 8 + (lane & 3) * 2;
                    sts_cluster64(dst + (uint32_t)(rl * 256 + col * 4),
                                  acc[mt][nt][0], acc[mt][nt][1]);
                    sts_cluster64(dst + (uint32_t)((rl + 8) * 256 + col * 4),
                                  acc[mt][nt][2], acc[mt][nt][3]);
                }
            }
        }

        // ---- Cluster barrier #2: peers' quarters landed in my slots ----
        CLUSTER_ARRIVE();
        CLUSTER_WAIT();

        // ---- Local reduce + elementwise ----
#pragma unroll
        for (int p = 0; p < 2; p++) {
            const int u_idx = uq + p * 4;
            const int u_local = r * 8 + u_idx;
            const int j = grp * 32 + u_local;
            float gate[4];
#pragma unroll
            for (int gg = 0; gg < 4; gg++) {
                const int off = (u_idx * 4 + gg) * 64 + bq;
                gate[gg] = slots[off] + slots[2048 + off]
                         + slots[4096 + off] + slots[6144 + off] + pv[p][gg];
            }
            const float gi = sigmoidf_(gate[0]);
            const float gf = sigmoidf_(gate[1]);
            const float gG = tanhf_(gate[2]);
            const float go = sigmoidf_(gate[3]);
            const float cnew = gf * cst[p] + gi * gG;
            cst[p] = cnew;
            const float hv = go * tanhf_(cnew);
            smHv[u_idx * 64 + bq] = hv;
            if (s == SEQ - 1) {
                hn[bq * HID + j] = hv;
                cn[bq * HID + j] = cnew;
            }
        }
        __syncthreads();

        // ---- Vectorized h / out writes (transposed through SMEM) ----
        {
            const int j0 = grp * 32 + r * 8;
            const int role = tid >> 6;       // 0:hh 1:hl 2:out/Ahi 3:-/Alo
            const int b = tid & 63;
            float hv8[8];
#pragma unroll
            for (int u = 0; u < 8; u++) hv8[u] = smHv[u * 64 + b];

            if (role == 0) {
                __nv_bfloat16 h8[8];
#pragma unroll
                for (int u = 0; u < 8; u++) h8[u] = __float2bfloat16_rn(hv8[u]);
                *reinterpret_cast<uint4*>(&g_hh[nb3][b * HID + j0]) =
                    *reinterpret_cast<uint4*>(h8);
            } else if (role == 1) {
                __nv_bfloat16 l8[8];
#pragma unroll
                for (int u = 0; u < 8; u++) {
                    __nv_bfloat16 h = __float2bfloat16_rn(hv8[u]);
                    l8[u] = __float2bfloat16_rn(hv8[u] - __bfloat162float(h));
                }
                *reinterpret_cast<uint4*>(&g_hl[nb3][b * HID + j0]) =
                    *reinterpret_cast<uint4*>(l8);
            } else if (role == 2) {
                if (out) {
                    float* o = &out[((size_t)(s * BATCH + b)) * HID + j0];
                    *reinterpret_cast<float4*>(o) =
                        make_float4(hv8[0], hv8[1], hv8[2], hv8[3]);
                    *reinterpret_cast<float4*>(o + 4) =
                        make_float4(hv8[4], hv8[5], hv8[6], hv8[7]);
                } else {
                    __nv_bfloat16 h8[8];
#pragma unroll
                    for (int u = 0; u < 8; u++) h8[u] = __float2bfloat16_rn(hv8[u]);
                    *reinterpret_cast<uint4*>(
                        &g_Ahi[((size_t)(s * BATCH + b)) * HID + j0]) =
                        *reinterpret_cast<uint4*>(h8);
                }
            } else {
                if (!out) {
                    __nv_bfloat16 l8[8];
#pragma unroll
                    for (int u = 0; u < 8; u++) {
                        __nv_bfloat16 h = __float2bfloat16_rn(hv8[u]);
                        l8[u] = __float2bfloat16_rn(hv8[u] - __bfloat162float(h));
                    }
                    *reinterpret_cast<uint4*>(
                        &g_Alo[((size_t)(s * BATCH + b)) * HID + j0]) =
                        *reinterpret_cast<uint4*>(l8);
                }
            }
        }
        __syncthreads();

        // ---- Release publish: group counter (no fence needed) ----
        if (tid == 0)
            asm volatile("red.release.gpu.global.add.u32 [%0], %1;"
                         :: "l"(&g_done[grp]), "r"(1u) : "memory");
    }
}

// ---------------------------------------------------------------------------
// Launch
// ---------------------------------------------------------------------------
extern "C" void kernel_launch(void* const* d_in, const int* in_sizes, int n_in,
                              void* d_out, int out_size)
{
    const float* x     = (const float*)d_in[0];
    const float* Wih0  = (const float*)d_in[1];
    const float* Whh0  = (const float*)d_in[2];
    const float* bih0  = (const float*)d_in[3];
    const float* bhh0  = (const float*)d_in[4];
    const float* Wih1  = (const float*)d_in[5];
    const float* Whh1  = (const float*)d_in[6];
    const float* bih1  = (const float*)d_in[7];
    const float* bhh1  = (const float*)d_in[8];

    float* out1 = (float*)d_out;
    float* hn   = out1 + (size_t)SEQ * BATCH * HID;
    float* cn   = hn + 2 * BATCH * HID;

    cudaFuncSetAttribute(mma_gemm_kernel,
                         cudaFuncAttributeMaxDynamicSharedMemorySize, GEMM_SMEM);
    cudaFuncSetAttribute(lstm_mma_kernel,
                         cudaFuncAttributeMaxDynamicSharedMemorySize, REC_SMEM);

    __nv_bfloat16 *Ahi, *Alo, *Whi, *Wlo;
    cudaGetSymbolAddress((void**)&Ahi, g_Ahi);
    cudaGetSymbolAddress((void**)&Alo, g_Alo);
    cudaGetSymbolAddress((void**)&Whi, g_Whi);
    cudaGetSymbolAddress((void**)&Wlo, g_Wlo);

    dim3 mgrid(MROWS / 128, G4 / 128);

    // ---- Layer 0 ----
    split_kernel<<<2048, 256>>>(x, Ahi, Alo, (MROWS * HID) / 4);
    split_kernel<<<512, 256>>>(Wih0, Whi, Wlo, (G4 * HID) / 4);
    zero_state_kernel<<<64, 256>>>();
    mma_gemm_kernel<<<mgrid, 256, GEMM_SMEM>>>(bih0, bhh0);
    lstm_mma_kernel<<<128, 256, REC_SMEM>>>(Whh0, nullptr, hn, cn);

    // ---- Layer 1 ----
    split_kernel<<<512, 256>>>(Wih1, Whi, Wlo, (G4 * HID) / 4);
    zero_state_kernel<<<64, 256>>>();
    mma_gemm_kernel<<<mgrid, 256, GEMM_SMEM>>>(bih1, bhh1);
    lstm_mma_kernel<<<128, 256, REC_SMEM>>>(Whh1, out1,
                                            hn + BATCH * HID,
                                            cn + BATCH * HID);
}